// round 9
// baseline (speedup 1.0000x reference)
#include <cuda_runtime.h>
#include <math.h>

typedef unsigned int uint;

#define PITCH   132      // activation smem pitch: bank = 4*row + k -> conflict-free frags
#define TPITCH  260      // MLP hidden tile pitch (260 % 32 == 4 -> same property)
#define THREADS 512

// ---------------------------------------------------------------------------
// Pre-converted, fragment-ordered tf32 weights (shared by all CTAs).
// Layout: idx = ((((kc*NCHUNKS + nc)*4 + ng)*8 + kk8)*32 + lane)*(2*NT) + 2*nt + which
//   value = tf32( W[kc*64 + kk8*8 + t + which*4][nc*NCH + ng*NT*8 + nt*8 + g] )
//   (g = lane>>2, t = lane&3)
// ---------------------------------------------------------------------------
#define OFF_PRE   0
#define OFF_QKV   8192
#define OFF_PROJ  57344
#define OFF_M1    73728
#define OFF_M2    106496
#define OFF_POST  139264
#define WFRAG_TOTAL 147456

__device__ uint g_wfrag[WFRAG_TOTAL];

__device__ __forceinline__ uint tf32r(float f){
    uint u; asm("cvt.rna.tf32.f32 %0, %1;" : "=r"(u) : "f"(f)); return u;
}
__device__ __forceinline__ float tf32f(float f){ return __uint_as_float(tf32r(f)); }

// grid-stride weight converter: one output uint per logical index
__global__ void convert_w_kernel(const float* __restrict__ W, int N, int NCH, int NT,
                                 int total, int dstoff)
{
    const int nchunks = N / NCH;
    for (int i = blockIdx.x * blockDim.x + threadIdx.x; i < total;
         i += gridDim.x * blockDim.x){
        int tmp = i;
        int which = tmp & 1;        tmp >>= 1;
        int nt    = tmp % NT;       tmp /= NT;
        int lane  = tmp & 31;       tmp >>= 5;
        int kk8   = tmp & 7;        tmp >>= 3;
        int ng    = tmp & 3;        tmp >>= 2;
        int nc    = tmp % nchunks;  tmp /= nchunks;
        int kc    = tmp;
        int g = lane >> 2, t = lane & 3;
        int row = kc * 64 + kk8 * 8 + t + which * 4;
        int col = nc * NCH + ng * NT * 8 + nt * 8 + g;
        g_wfrag[dstoff + i] = tf32r(W[(size_t)row * N + col]);
    }
}

// m16n8k8 tf32 MMA, fp32 accumulate
__device__ __forceinline__ void mma8(float (&c)[4],
                                     uint a0, uint a1, uint a2, uint a3,
                                     uint b0, uint b1){
    asm("mma.sync.aligned.m16n8k8.row.col.f32.tf32.tf32.f32 "
        "{%0,%1,%2,%3}, {%4,%5,%6,%7}, {%8,%9}, {%0,%1,%2,%3};"
        : "+f"(c[0]), "+f"(c[1]), "+f"(c[2]), "+f"(c[3])
        : "r"(a0), "r"(a1), "r"(a2), "r"(a3), "r"(b0), "r"(b1));
}

// ---------------------------------------------------------------------------
// GEMM over one n-chunk using fragment-ordered global weights (no staging).
// Warp (mg, ng): rows mg*16..+15, cols ng*NT*8..+NT*8-1 within the chunk.
// ---------------------------------------------------------------------------
template<int KTOT, int NT, int NCHUNKS, bool CVT_A>
__device__ __forceinline__ void gemm_g(const float* __restrict__ As, int apitch,
                                       const uint* __restrict__ Wf, int nchunk,
                                       int tid, float (&c)[NT][4])
{
    const int warp = tid >> 5, lane = tid & 31;
    const int g = lane >> 2, t = lane & 3;
    const int mg = warp >> 2, ng = warp & 3;

#pragma unroll
    for (int nt = 0; nt < NT; nt++)
#pragma unroll
        for (int i = 0; i < 4; i++) c[nt][i] = 0.f;

    const float* a0p = As + (mg * 16 + g) * apitch + t;
    const float* a1p = a0p + 8 * apitch;

    constexpr int LSTRIDE = 2 * NT;                 // uints per lane per kk8
    constexpr int KKSTRIDE = 32 * LSTRIDE;          // per kk8 step
    constexpr int KCSTRIDE = NCHUNKS * 4 * 8 * KKSTRIDE / 8; // careful: per kchunk
    // per kchunk stride = NCHUNKS * 4(ng) * 8(kk8) * KKSTRIDE/ (kk8 factor already in) :
    // full: NCHUNKS*4*8*32*2*NT
    const uint* wbase = Wf + ((nchunk * 4 + ng) * 8) * KKSTRIDE + lane * LSTRIDE;

#pragma unroll
    for (int kc = 0; kc < KTOT / 64; kc++){
        const uint* wkc = wbase + kc * (NCHUNKS * 4 * 8 * KKSTRIDE);
#pragma unroll
        for (int kk8 = 0; kk8 < 8; kk8++){
            const int k = kc * 64 + kk8 * 8;
            float f0 = a0p[k],     f1 = a1p[k];
            float f2 = a0p[k + 4], f3 = a1p[k + 4];
            uint a0, a1, a2, a3;
            if (CVT_A){ a0 = tf32r(f0); a1 = tf32r(f1); a2 = tf32r(f2); a3 = tf32r(f3); }
            else      { a0 = __float_as_uint(f0); a1 = __float_as_uint(f1);
                        a2 = __float_as_uint(f2); a3 = __float_as_uint(f3); }
            const uint4* bp = (const uint4*)(wkc + kk8 * KKSTRIDE);
#pragma unroll
            for (int p = 0; p < NT / 2; p++){
                uint4 bv = bp[p];
                mma8(c[2*p],     a0, a1, a2, a3, bv.x, bv.y);
                mma8(c[2*p + 1], a0, a1, a2, a3, bv.z, bv.w);
            }
        }
    }
    (void)KCSTRIDE;
}

// ---------------------------------------------------------------------------
// LayerNorm over 128 cols -> tf32-rounded output
// ---------------------------------------------------------------------------
__device__ __forceinline__ void layernorm(const float* __restrict__ Xs, float* __restrict__ Ns,
                                          const float* __restrict__ g, const float* __restrict__ b,
                                          int tid)
{
    const int row = tid >> 3, sub = tid & 7;
    const float* xr = Xs + row * PITCH;
    float s = 0.f, s2 = 0.f;
#pragma unroll
    for (int i = 0; i < 16; i++){
        float v = xr[sub + i * 8];
        s += v; s2 = fmaf(v, v, s2);
    }
#pragma unroll
    for (int o = 4; o; o >>= 1){
        s  += __shfl_xor_sync(0xffffffffu, s,  o);
        s2 += __shfl_xor_sync(0xffffffffu, s2, o);
    }
    float mu  = s  * (1.f / 128.f);
    float var = s2 * (1.f / 128.f) - mu * mu;
    float rs  = rsqrtf(var + 1e-5f);
    float* nr = Ns + row * PITCH;
#pragma unroll
    for (int i = 0; i < 16; i++){
        int c = sub + i * 8;
        nr[c] = tf32f((xr[c] - mu) * rs * g[c] + b[c]);
    }
}

// ---------------------------------------------------------------------------
// Windowed attention on the tensor pipe (unchanged from R6).
// ---------------------------------------------------------------------------
__device__ __forceinline__ void attention_phase(float* Qs, const float* Ks, const float* Vs, int tid)
{
    const int warp = tid >> 5;
    const int lane = tid & 31;
    const int g = lane >> 2, t = lane & 3;
    const int h = warp >> 1;
    const int s = warp & 1;
    const int co = h * 16;

    const int src0 = (lane & 28) | (t >> 1);
    const int src1 = src0 + 2;
    const bool odd = (t & 1);

#pragma unroll
    for (int mt = 0; mt < 2; mt++){
        const int m0 = s * 32 + mt * 16;

        float sc[8][4];
#pragma unroll
        for (int nb = 0; nb < 8; nb++){
            sc[nb][0] = sc[nb][1] = sc[nb][2] = sc[nb][3] = 0.f;
        }
#pragma unroll
        for (int k0 = 0; k0 < 16; k0 += 8){
            const float* qp = Qs + (m0 + g) * PITCH + co + k0 + t;
            uint a0 = __float_as_uint(qp[0]);
            uint a1 = __float_as_uint(qp[8 * PITCH]);
            uint a2 = __float_as_uint(qp[4]);
            uint a3 = __float_as_uint(qp[8 * PITCH + 4]);
#pragma unroll
            for (int nb = 0; nb < 8; nb++){
                const float* kp = Ks + (8 * nb + g) * PITCH + co + k0 + t;
                uint b0 = __float_as_uint(kp[0]);
                uint b1 = __float_as_uint(kp[4]);
                mma8(sc[nb], a0, a1, a2, a3, b0, b1);
            }
        }

        float mx0 = -1e30f, mx1 = -1e30f;
#pragma unroll
        for (int nb = 0; nb < 8; nb++){
            mx0 = fmaxf(mx0, fmaxf(sc[nb][0], sc[nb][1]));
            mx1 = fmaxf(mx1, fmaxf(sc[nb][2], sc[nb][3]));
        }
        mx0 = fmaxf(mx0, __shfl_xor_sync(0xffffffffu, mx0, 1));
        mx0 = fmaxf(mx0, __shfl_xor_sync(0xffffffffu, mx0, 2));
        mx1 = fmaxf(mx1, __shfl_xor_sync(0xffffffffu, mx1, 1));
        mx1 = fmaxf(mx1, __shfl_xor_sync(0xffffffffu, mx1, 2));

        float l0 = 0.f, l1 = 0.f;
#pragma unroll
        for (int nb = 0; nb < 8; nb++){
            float p0 = __expf((sc[nb][0] - mx0) * 0.25f);
            float p1 = __expf((sc[nb][1] - mx0) * 0.25f);
            float p2 = __expf((sc[nb][2] - mx1) * 0.25f);
            float p3 = __expf((sc[nb][3] - mx1) * 0.25f);
            l0 += p0 + p1;  l1 += p2 + p3;
            sc[nb][0] = __uint_as_float(tf32r(p0));
            sc[nb][1] = __uint_as_float(tf32r(p1));
            sc[nb][2] = __uint_as_float(tf32r(p2));
            sc[nb][3] = __uint_as_float(tf32r(p3));
        }
        l0 += __shfl_xor_sync(0xffffffffu, l0, 1);
        l0 += __shfl_xor_sync(0xffffffffu, l0, 2);
        l1 += __shfl_xor_sync(0xffffffffu, l1, 1);
        l1 += __shfl_xor_sync(0xffffffffu, l1, 2);

        float oc[2][4];
        oc[0][0]=oc[0][1]=oc[0][2]=oc[0][3]=0.f;
        oc[1][0]=oc[1][1]=oc[1][2]=oc[1][3]=0.f;
#pragma unroll
        for (int kb = 0; kb < 8; kb++){
            float p0 = sc[kb][0], p1 = sc[kb][1], p2 = sc[kb][2], p3 = sc[kb][3];
            float q00 = __shfl_sync(0xffffffffu, p0, src0);
            float q01 = __shfl_sync(0xffffffffu, p1, src0);
            float q02 = __shfl_sync(0xffffffffu, p0, src1);
            float q03 = __shfl_sync(0xffffffffu, p1, src1);
            float q10 = __shfl_sync(0xffffffffu, p2, src0);
            float q11 = __shfl_sync(0xffffffffu, p3, src0);
            float q12 = __shfl_sync(0xffffffffu, p2, src1);
            float q13 = __shfl_sync(0xffffffffu, p3, src1);
            uint a0 = __float_as_uint(odd ? q01 : q00);
            uint a1 = __float_as_uint(odd ? q11 : q10);
            uint a2 = __float_as_uint(odd ? q03 : q02);
            uint a3 = __float_as_uint(odd ? q13 : q12);
#pragma unroll
            for (int nb2 = 0; nb2 < 2; nb2++){
                const float* vp = Vs + (8 * kb + t) * PITCH + co + nb2 * 8 + g;
                uint b0 = __float_as_uint(vp[0]);
                uint b1 = __float_as_uint(vp[4 * PITCH]);
                mma8(oc[nb2], a0, a1, a2, a3, b0, b1);
            }
        }
        float i0 = 1.0f / l0, i1 = 1.0f / l1;
#pragma unroll
        for (int nb2 = 0; nb2 < 2; nb2++){
            float* op0 = Qs + (m0 + g) * PITCH + co + nb2 * 8 + 2 * t;
            float* op1 = op0 + 8 * PITCH;
            *(float2*)op0 = make_float2(oc[nb2][0] * i0, oc[nb2][1] * i0);
            *(float2*)op1 = make_float2(oc[nb2][2] * i1, oc[nb2][3] * i1);
        }
    }
}

// ---------------------------------------------------------------------------
// Fused transformer block: one CTA = one 64-token window.
// ---------------------------------------------------------------------------
extern __shared__ float smbuf[];

__global__ void __launch_bounds__(THREADS, 1)
fused_block_kernel(const float* __restrict__ feats,
                   const float* __restrict__ b_pre,
                   const float* __restrict__ g1,   const float* __restrict__ b1,
                   const float* __restrict__ b_qkv,
                   const float* __restrict__ b_proj,
                   const float* __restrict__ g2,   const float* __restrict__ b2,
                   const float* __restrict__ b_m1, const float* __restrict__ b_m2,
                   const float* __restrict__ b_post,
                   float* __restrict__ out)
{
    float* Xs = smbuf;                  // residual stream (fp32)     [64][132]
    float* Ns = smbuf + 64 * PITCH;     // LN out / staged feats (tf32-rounded)
    float* Qs = smbuf + 2 * 64 * PITCH; // q -> attention output o
    float* Ks = smbuf + 3 * 64 * PITCH; // k -> MLP hidden (pitch 260 spans Ks+Vs)
    float* Vs = smbuf + 4 * 64 * PITCH; // v
    float* Ts = Ks;

    const int tid  = threadIdx.x;
    const int warp = tid >> 5, lane = tid & 31;
    const int g    = lane >> 2, t = lane & 3;
    const int mg   = warp >> 2, ng = warp & 3;
    const int r0   = mg * 16 + g;
    const size_t tok0 = (size_t)blockIdx.x * 64;

    // stage feats tile [64][64] into Ns cols 0..63 (tf32-rounded)
    for (int i = tid; i < 64 * 16; i += THREADS){
        int tk = i >> 4, c4 = i & 15;
        float4 v = ((const float4*)(feats + (tok0 + tk) * 64))[c4];
        uint4 o = make_uint4(tf32r(v.x), tf32r(v.y), tf32r(v.z), tf32r(v.w));
        *(uint4*)((uint*)Ns + tk * PITCH + c4 * 4) = o;
    }
    __syncthreads();

    // ---- pre: x2 = feats @ w_pre + b_pre  (K=64 -> N=128) ----
    {
        float c[4][4];
        gemm_g<64, 4, 1, false>(Ns, PITCH, g_wfrag + OFF_PRE, 0, tid, c);
#pragma unroll
        for (int nt = 0; nt < 4; nt++){
            int col = ng * 32 + nt * 8 + 2 * t;
            float2 bv = *(const float2*)(b_pre + col);
            *(float2*)(Xs + r0 * PITCH + col)       = make_float2(c[nt][0] + bv.x, c[nt][1] + bv.y);
            *(float2*)(Xs + (r0 + 8) * PITCH + col) = make_float2(c[nt][2] + bv.x, c[nt][3] + bv.y);
        }
    }
    __syncthreads();
    layernorm(Xs, Ns, g1, b1, tid);
    __syncthreads();

    // ---- qkv: 3 col-chunks of w_qkv (N=384), K=128 ----
    {
        float* dsts[3] = {Qs, Ks, Vs};
#pragma unroll
        for (int ch = 0; ch < 3; ch++){
            float c[4][4];
            gemm_g<128, 4, 3, false>(Ns, PITCH, g_wfrag + OFF_QKV, ch, tid, c);
            float* dst = dsts[ch];
#pragma unroll
            for (int nt = 0; nt < 4; nt++){
                int col = ng * 32 + nt * 8 + 2 * t;
                float2 bv = *(const float2*)(b_qkv + ch * 128 + col);
                *(float2*)(dst + r0 * PITCH + col) =
                    make_float2(tf32f(c[nt][0] + bv.x), tf32f(c[nt][1] + bv.y));
                *(float2*)(dst + (r0 + 8) * PITCH + col) =
                    make_float2(tf32f(c[nt][2] + bv.x), tf32f(c[nt][3] + bv.y));
            }
        }
    }
    __syncthreads();

    attention_phase(Qs, Ks, Vs, tid);   // o -> Qs (fp32), tensor-pipe MMA
    __syncthreads();

    // ---- proj + residual: x2 += o @ w_proj + b_proj ----
    {
        float c[4][4];
        gemm_g<128, 4, 1, true>(Qs, PITCH, g_wfrag + OFF_PROJ, 0, tid, c);
#pragma unroll
        for (int nt = 0; nt < 4; nt++){
            int col = ng * 32 + nt * 8 + 2 * t;
            float2 bv = *(const float2*)(b_proj + col);
            float2* p0 = (float2*)(Xs + r0 * PITCH + col);
            float2* p1 = (float2*)(Xs + (r0 + 8) * PITCH + col);
            float2 v0 = *p0, v1 = *p1;
            v0.x += c[nt][0] + bv.x; v0.y += c[nt][1] + bv.y;
            v1.x += c[nt][2] + bv.x; v1.y += c[nt][3] + bv.y;
            *p0 = v0; *p1 = v1;
        }
    }
    __syncthreads();
    layernorm(Xs, Ns, g2, b2, tid);
    __syncthreads();

    // ---- mlp1: t = gelu(n2 @ w_m1 + b_m1)  (N=256: 2 col-chunks) ----
#pragma unroll
    for (int ch = 0; ch < 2; ch++){
        float c[4][4];
        gemm_g<128, 4, 2, false>(Ns, PITCH, g_wfrag + OFF_M1, ch, tid, c);
#pragma unroll
        for (int nt = 0; nt < 4; nt++){
            int col = ng * 32 + nt * 8 + 2 * t;
            float2 bv = *(const float2*)(b_m1 + ch * 128 + col);
            float v[4] = {c[nt][0] + bv.x, c[nt][1] + bv.y,
                          c[nt][2] + bv.x, c[nt][3] + bv.y};
#pragma unroll
            for (int i = 0; i < 4; i++)
                v[i] = tf32f(0.5f * v[i] * (1.0f + erff(v[i] * 0.70710678118654752f)));
            *(float2*)(Ts + r0 * TPITCH + ch * 128 + col)       = make_float2(v[0], v[1]);
            *(float2*)(Ts + (r0 + 8) * TPITCH + ch * 128 + col) = make_float2(v[2], v[3]);
        }
    }
    __syncthreads();

    // ---- mlp2 + residual: x2 += t @ w_m2 + b_m2  (K=256) ----
    {
        float c[4][4];
        gemm_g<256, 4, 1, false>(Ts, TPITCH, g_wfrag + OFF_M2, 0, tid, c);
#pragma unroll
        for (int nt = 0; nt < 4; nt++){
            int col = ng * 32 + nt * 8 + 2 * t;
            float2 bv = *(const float2*)(b_m2 + col);
            float2* p0 = (float2*)(Xs + r0 * PITCH + col);
            float2* p1 = (float2*)(Xs + (r0 + 8) * PITCH + col);
            float2 v0 = *p0, v1 = *p1;
            v0.x += c[nt][0] + bv.x; v0.y += c[nt][1] + bv.y;
            v1.x += c[nt][2] + bv.x; v1.y += c[nt][3] + bv.y;
            *p0 = v0; *p1 = v1;
        }
    }
    __syncthreads();

    // ---- post: out = x2 @ w_post + b_post  (N=64, NT=2) ----
    {
        float c[2][4];
        gemm_g<128, 2, 1, true>(Xs, PITCH, g_wfrag + OFF_POST, 0, tid, c);
#pragma unroll
        for (int nt = 0; nt < 2; nt++){
            int col = ng * 16 + nt * 8 + 2 * t;
            float2 bv = *(const float2*)(b_post + col);
            *(float2*)(out + (tok0 + r0) * 64 + col) =
                make_float2(c[nt][0] + bv.x, c[nt][1] + bv.y);
            *(float2*)(out + (tok0 + r0 + 8) * 64 + col) =
                make_float2(c[nt][2] + bv.x, c[nt][3] + bv.y);
        }
    }
}

extern "C" void kernel_launch(void* const* d_in, const int* in_sizes, int n_in,
                              void* d_out, int out_size)
{
    const float* feats  = (const float*)d_in[0];
    const float* w_pre  = (const float*)d_in[1];
    const float* b_pre  = (const float*)d_in[2];
    const float* g1     = (const float*)d_in[3];
    const float* b1     = (const float*)d_in[4];
    const float* w_qkv  = (const float*)d_in[5];
    const float* b_qkv  = (const float*)d_in[6];
    const float* w_proj = (const float*)d_in[7];
    const float* b_proj = (const float*)d_in[8];
    const float* g2     = (const float*)d_in[9];
    const float* b2     = (const float*)d_in[10];
    const float* w_m1   = (const float*)d_in[11];
    const float* b_m1   = (const float*)d_in[12];
    const float* w_m2   = (const float*)d_in[13];
    const float* b_m2   = (const float*)d_in[14];
    const float* w_post = (const float*)d_in[15];
    const float* b_post = (const float*)d_in[16];
    float* out = (float*)d_out;

    // fragment-order + tf32 conversion of all weights (runs each replay; cheap)
    convert_w_kernel<<<64, 256>>>(w_pre,  128, 128, 4,  8192, OFF_PRE);
    convert_w_kernel<<<96, 256>>>(w_qkv,  384, 128, 4, 49152, OFF_QKV);
    convert_w_kernel<<<64, 256>>>(w_proj, 128, 128, 4, 16384, OFF_PROJ);
    convert_w_kernel<<<96, 256>>>(w_m1,   256, 128, 4, 32768, OFF_M1);
    convert_w_kernel<<<96, 256>>>(w_m2,   128, 128, 4, 32768, OFF_M2);
    convert_w_kernel<<<64, 256>>>(w_post,  64,  64, 2,  8192, OFF_POST);

    const int ntok    = in_sizes[0] / 64;   // C = 64
    const int nblocks = ntok / 64;          // PS = 64 tokens per window
    const size_t smem = (size_t)(5 * 64 * PITCH) * sizeof(float);   // 168960 B

    cudaFuncSetAttribute(fused_block_kernel,
                         cudaFuncAttributeMaxDynamicSharedMemorySize, (int)smem);

    fused_block_kernel<<<nblocks, THREADS, smem>>>(feats, b_pre, g1, b1,
                                                   b_qkv, b_proj, g2, b2,
                                                   b_m1, b_m2, b_post, out);
}

// round 10
// speedup vs baseline: 1.0023x; 1.0023x over previous
#include <cuda_runtime.h>
#include <math.h>

typedef unsigned int uint;

#define PITCH   132      // activation smem pitch: bank = 4*row + k -> conflict-free frags
#define TPITCH  260      // MLP hidden tile pitch (260 % 32 == 4 -> same property)
#define THREADS 512

// ---------------------------------------------------------------------------
// Pre-converted, fragment-ordered tf32 weights (shared by all CTAs).
// Layout: idx = ((((kc*NCHUNKS + nc)*4 + ng)*8 + kk8)*32 + lane)*(2*NT) + 2*nt + which
//   value = tf32( W[kc*64 + kk8*8 + t + which*4][nc*NCH + ng*NT*8 + nt*8 + g] )
//   (g = lane>>2, t = lane&3)
// ---------------------------------------------------------------------------
#define OFF_PRE   0
#define OFF_QKV   8192
#define OFF_PROJ  57344
#define OFF_M1    73728
#define OFF_M2    106496
#define OFF_POST  139264
#define WFRAG_TOTAL 147456

__device__ uint g_wfrag[WFRAG_TOTAL];

__device__ __forceinline__ uint tf32r(float f){
    uint u; asm("cvt.rna.tf32.f32 %0, %1;" : "=r"(u) : "f"(f)); return u;
}
__device__ __forceinline__ float tf32f(float f){ return __uint_as_float(tf32r(f)); }

// grid-stride weight converter: one output uint per logical index
__global__ void convert_w_kernel(const float* __restrict__ W, int N, int NCH, int NT,
                                 int total, int dstoff)
{
    const int nchunks = N / NCH;
    for (int i = blockIdx.x * blockDim.x + threadIdx.x; i < total;
         i += gridDim.x * blockDim.x){
        int tmp = i;
        int which = tmp & 1;        tmp >>= 1;
        int nt    = tmp % NT;       tmp /= NT;
        int lane  = tmp & 31;       tmp >>= 5;
        int kk8   = tmp & 7;        tmp >>= 3;
        int ng    = tmp & 3;        tmp >>= 2;
        int nc    = tmp % nchunks;  tmp /= nchunks;
        int kc    = tmp;
        int g = lane >> 2, t = lane & 3;
        int row = kc * 64 + kk8 * 8 + t + which * 4;
        int col = nc * NCH + ng * NT * 8 + nt * 8 + g;
        g_wfrag[dstoff + i] = tf32r(W[(size_t)row * N + col]);
    }
}

// m16n8k8 tf32 MMA, fp32 accumulate
__device__ __forceinline__ void mma8(float (&c)[4],
                                     uint a0, uint a1, uint a2, uint a3,
                                     uint b0, uint b1){
    asm("mma.sync.aligned.m16n8k8.row.col.f32.tf32.tf32.f32 "
        "{%0,%1,%2,%3}, {%4,%5,%6,%7}, {%8,%9}, {%0,%1,%2,%3};"
        : "+f"(c[0]), "+f"(c[1]), "+f"(c[2]), "+f"(c[3])
        : "r"(a0), "r"(a1), "r"(a2), "r"(a3), "r"(b0), "r"(b1));
}

// ---------------------------------------------------------------------------
// GEMM over one n-chunk using fragment-ordered global weights (no staging).
// Warp (mg, ng): rows mg*16..+15, cols ng*NT*8..+NT*8-1 within the chunk.
// ---------------------------------------------------------------------------
template<int KTOT, int NT, int NCHUNKS, bool CVT_A>
__device__ __forceinline__ void gemm_g(const float* __restrict__ As, int apitch,
                                       const uint* __restrict__ Wf, int nchunk,
                                       int tid, float (&c)[NT][4])
{
    const int warp = tid >> 5, lane = tid & 31;
    const int g = lane >> 2, t = lane & 3;
    const int mg = warp >> 2, ng = warp & 3;

#pragma unroll
    for (int nt = 0; nt < NT; nt++)
#pragma unroll
        for (int i = 0; i < 4; i++) c[nt][i] = 0.f;

    const float* a0p = As + (mg * 16 + g) * apitch + t;
    const float* a1p = a0p + 8 * apitch;

    constexpr int LSTRIDE = 2 * NT;                 // uints per lane per kk8
    constexpr int KKSTRIDE = 32 * LSTRIDE;          // per kk8 step
    constexpr int KCSTRIDE = NCHUNKS * 4 * 8 * KKSTRIDE / 8; // careful: per kchunk
    // per kchunk stride = NCHUNKS * 4(ng) * 8(kk8) * KKSTRIDE/ (kk8 factor already in) :
    // full: NCHUNKS*4*8*32*2*NT
    const uint* wbase = Wf + ((nchunk * 4 + ng) * 8) * KKSTRIDE + lane * LSTRIDE;

#pragma unroll
    for (int kc = 0; kc < KTOT / 64; kc++){
        const uint* wkc = wbase + kc * (NCHUNKS * 4 * 8 * KKSTRIDE);
#pragma unroll
        for (int kk8 = 0; kk8 < 8; kk8++){
            const int k = kc * 64 + kk8 * 8;
            float f0 = a0p[k],     f1 = a1p[k];
            float f2 = a0p[k + 4], f3 = a1p[k + 4];
            uint a0, a1, a2, a3;
            if (CVT_A){ a0 = tf32r(f0); a1 = tf32r(f1); a2 = tf32r(f2); a3 = tf32r(f3); }
            else      { a0 = __float_as_uint(f0); a1 = __float_as_uint(f1);
                        a2 = __float_as_uint(f2); a3 = __float_as_uint(f3); }
            const uint4* bp = (const uint4*)(wkc + kk8 * KKSTRIDE);
#pragma unroll
            for (int p = 0; p < NT / 2; p++){
                uint4 bv = bp[p];
                mma8(c[2*p],     a0, a1, a2, a3, bv.x, bv.y);
                mma8(c[2*p + 1], a0, a1, a2, a3, bv.z, bv.w);
            }
        }
    }
    (void)KCSTRIDE;
}

// ---------------------------------------------------------------------------
// LayerNorm over 128 cols -> tf32-rounded output
// ---------------------------------------------------------------------------
__device__ __forceinline__ void layernorm(const float* __restrict__ Xs, float* __restrict__ Ns,
                                          const float* __restrict__ g, const float* __restrict__ b,
                                          int tid)
{
    const int row = tid >> 3, sub = tid & 7;
    const float* xr = Xs + row * PITCH;
    float s = 0.f, s2 = 0.f;
#pragma unroll
    for (int i = 0; i < 16; i++){
        float v = xr[sub + i * 8];
        s += v; s2 = fmaf(v, v, s2);
    }
#pragma unroll
    for (int o = 4; o; o >>= 1){
        s  += __shfl_xor_sync(0xffffffffu, s,  o);
        s2 += __shfl_xor_sync(0xffffffffu, s2, o);
    }
    float mu  = s  * (1.f / 128.f);
    float var = s2 * (1.f / 128.f) - mu * mu;
    float rs  = rsqrtf(var + 1e-5f);
    float* nr = Ns + row * PITCH;
#pragma unroll
    for (int i = 0; i < 16; i++){
        int c = sub + i * 8;
        nr[c] = tf32f((xr[c] - mu) * rs * g[c] + b[c]);
    }
}

// ---------------------------------------------------------------------------
// Windowed attention on the tensor pipe (unchanged from R6).
// ---------------------------------------------------------------------------
__device__ __forceinline__ void attention_phase(float* Qs, const float* Ks, const float* Vs, int tid)
{
    const int warp = tid >> 5;
    const int lane = tid & 31;
    const int g = lane >> 2, t = lane & 3;
    const int h = warp >> 1;
    const int s = warp & 1;
    const int co = h * 16;

    const int src0 = (lane & 28) | (t >> 1);
    const int src1 = src0 + 2;
    const bool odd = (t & 1);

#pragma unroll
    for (int mt = 0; mt < 2; mt++){
        const int m0 = s * 32 + mt * 16;

        float sc[8][4];
#pragma unroll
        for (int nb = 0; nb < 8; nb++){
            sc[nb][0] = sc[nb][1] = sc[nb][2] = sc[nb][3] = 0.f;
        }
#pragma unroll
        for (int k0 = 0; k0 < 16; k0 += 8){
            const float* qp = Qs + (m0 + g) * PITCH + co + k0 + t;
            uint a0 = __float_as_uint(qp[0]);
            uint a1 = __float_as_uint(qp[8 * PITCH]);
            uint a2 = __float_as_uint(qp[4]);
            uint a3 = __float_as_uint(qp[8 * PITCH + 4]);
#pragma unroll
            for (int nb = 0; nb < 8; nb++){
                const float* kp = Ks + (8 * nb + g) * PITCH + co + k0 + t;
                uint b0 = __float_as_uint(kp[0]);
                uint b1 = __float_as_uint(kp[4]);
                mma8(sc[nb], a0, a1, a2, a3, b0, b1);
            }
        }

        float mx0 = -1e30f, mx1 = -1e30f;
#pragma unroll
        for (int nb = 0; nb < 8; nb++){
            mx0 = fmaxf(mx0, fmaxf(sc[nb][0], sc[nb][1]));
            mx1 = fmaxf(mx1, fmaxf(sc[nb][2], sc[nb][3]));
        }
        mx0 = fmaxf(mx0, __shfl_xor_sync(0xffffffffu, mx0, 1));
        mx0 = fmaxf(mx0, __shfl_xor_sync(0xffffffffu, mx0, 2));
        mx1 = fmaxf(mx1, __shfl_xor_sync(0xffffffffu, mx1, 1));
        mx1 = fmaxf(mx1, __shfl_xor_sync(0xffffffffu, mx1, 2));

        float l0 = 0.f, l1 = 0.f;
#pragma unroll
        for (int nb = 0; nb < 8; nb++){
            float p0 = __expf((sc[nb][0] - mx0) * 0.25f);
            float p1 = __expf((sc[nb][1] - mx0) * 0.25f);
            float p2 = __expf((sc[nb][2] - mx1) * 0.25f);
            float p3 = __expf((sc[nb][3] - mx1) * 0.25f);
            l0 += p0 + p1;  l1 += p2 + p3;
            sc[nb][0] = __uint_as_float(tf32r(p0));
            sc[nb][1] = __uint_as_float(tf32r(p1));
            sc[nb][2] = __uint_as_float(tf32r(p2));
            sc[nb][3] = __uint_as_float(tf32r(p3));
        }
        l0 += __shfl_xor_sync(0xffffffffu, l0, 1);
        l0 += __shfl_xor_sync(0xffffffffu, l0, 2);
        l1 += __shfl_xor_sync(0xffffffffu, l1, 1);
        l1 += __shfl_xor_sync(0xffffffffu, l1, 2);

        float oc[2][4];
        oc[0][0]=oc[0][1]=oc[0][2]=oc[0][3]=0.f;
        oc[1][0]=oc[1][1]=oc[1][2]=oc[1][3]=0.f;
#pragma unroll
        for (int kb = 0; kb < 8; kb++){
            float p0 = sc[kb][0], p1 = sc[kb][1], p2 = sc[kb][2], p3 = sc[kb][3];
            float q00 = __shfl_sync(0xffffffffu, p0, src0);
            float q01 = __shfl_sync(0xffffffffu, p1, src0);
            float q02 = __shfl_sync(0xffffffffu, p0, src1);
            float q03 = __shfl_sync(0xffffffffu, p1, src1);
            float q10 = __shfl_sync(0xffffffffu, p2, src0);
            float q11 = __shfl_sync(0xffffffffu, p3, src0);
            float q12 = __shfl_sync(0xffffffffu, p2, src1);
            float q13 = __shfl_sync(0xffffffffu, p3, src1);
            uint a0 = __float_as_uint(odd ? q01 : q00);
            uint a1 = __float_as_uint(odd ? q11 : q10);
            uint a2 = __float_as_uint(odd ? q03 : q02);
            uint a3 = __float_as_uint(odd ? q13 : q12);
#pragma unroll
            for (int nb2 = 0; nb2 < 2; nb2++){
                const float* vp = Vs + (8 * kb + t) * PITCH + co + nb2 * 8 + g;
                uint b0 = __float_as_uint(vp[0]);
                uint b1 = __float_as_uint(vp[4 * PITCH]);
                mma8(oc[nb2], a0, a1, a2, a3, b0, b1);
            }
        }
        float i0 = 1.0f / l0, i1 = 1.0f / l1;
#pragma unroll
        for (int nb2 = 0; nb2 < 2; nb2++){
            float* op0 = Qs + (m0 + g) * PITCH + co + nb2 * 8 + 2 * t;
            float* op1 = op0 + 8 * PITCH;
            *(float2*)op0 = make_float2(oc[nb2][0] * i0, oc[nb2][1] * i0);
            *(float2*)op1 = make_float2(oc[nb2][2] * i1, oc[nb2][3] * i1);
        }
    }
}

// ---------------------------------------------------------------------------
// Fused transformer block: one CTA = one 64-token window.
// ---------------------------------------------------------------------------
extern __shared__ float smbuf[];

__global__ void __launch_bounds__(THREADS, 1)
fused_block_kernel(const float* __restrict__ feats,
                   const float* __restrict__ b_pre,
                   const float* __restrict__ g1,   const float* __restrict__ b1,
                   const float* __restrict__ b_qkv,
                   const float* __restrict__ b_proj,
                   const float* __restrict__ g2,   const float* __restrict__ b2,
                   const float* __restrict__ b_m1, const float* __restrict__ b_m2,
                   const float* __restrict__ b_post,
                   float* __restrict__ out)
{
    float* Xs = smbuf;                  // residual stream (fp32)     [64][132]
    float* Ns = smbuf + 64 * PITCH;     // LN out / staged feats (tf32-rounded)
    float* Qs = smbuf + 2 * 64 * PITCH; // q -> attention output o
    float* Ks = smbuf + 3 * 64 * PITCH; // k -> MLP hidden (pitch 260 spans Ks+Vs)
    float* Vs = smbuf + 4 * 64 * PITCH; // v
    float* Ts = Ks;

    const int tid  = threadIdx.x;
    const int warp = tid >> 5, lane = tid & 31;
    const int g    = lane >> 2, t = lane & 3;
    const int mg   = warp >> 2, ng = warp & 3;
    const int r0   = mg * 16 + g;
    const size_t tok0 = (size_t)blockIdx.x * 64;

    // stage feats tile [64][64] into Ns cols 0..63 (tf32-rounded)
    for (int i = tid; i < 64 * 16; i += THREADS){
        int tk = i >> 4, c4 = i & 15;
        float4 v = ((const float4*)(feats + (tok0 + tk) * 64))[c4];
        uint4 o = make_uint4(tf32r(v.x), tf32r(v.y), tf32r(v.z), tf32r(v.w));
        *(uint4*)((uint*)Ns + tk * PITCH + c4 * 4) = o;
    }
    __syncthreads();

    // ---- pre: x2 = feats @ w_pre + b_pre  (K=64 -> N=128) ----
    {
        float c[4][4];
        gemm_g<64, 4, 1, false>(Ns, PITCH, g_wfrag + OFF_PRE, 0, tid, c);
#pragma unroll
        for (int nt = 0; nt < 4; nt++){
            int col = ng * 32 + nt * 8 + 2 * t;
            float2 bv = *(const float2*)(b_pre + col);
            *(float2*)(Xs + r0 * PITCH + col)       = make_float2(c[nt][0] + bv.x, c[nt][1] + bv.y);
            *(float2*)(Xs + (r0 + 8) * PITCH + col) = make_float2(c[nt][2] + bv.x, c[nt][3] + bv.y);
        }
    }
    __syncthreads();
    layernorm(Xs, Ns, g1, b1, tid);
    __syncthreads();

    // ---- qkv: 3 col-chunks of w_qkv (N=384), K=128 ----
    {
        float* dsts[3] = {Qs, Ks, Vs};
#pragma unroll
        for (int ch = 0; ch < 3; ch++){
            float c[4][4];
            gemm_g<128, 4, 3, false>(Ns, PITCH, g_wfrag + OFF_QKV, ch, tid, c);
            float* dst = dsts[ch];
#pragma unroll
            for (int nt = 0; nt < 4; nt++){
                int col = ng * 32 + nt * 8 + 2 * t;
                float2 bv = *(const float2*)(b_qkv + ch * 128 + col);
                *(float2*)(dst + r0 * PITCH + col) =
                    make_float2(tf32f(c[nt][0] + bv.x), tf32f(c[nt][1] + bv.y));
                *(float2*)(dst + (r0 + 8) * PITCH + col) =
                    make_float2(tf32f(c[nt][2] + bv.x), tf32f(c[nt][3] + bv.y));
            }
        }
    }
    __syncthreads();

    attention_phase(Qs, Ks, Vs, tid);   // o -> Qs (fp32), tensor-pipe MMA
    __syncthreads();

    // ---- proj + residual: x2 += o @ w_proj + b_proj ----
    {
        float c[4][4];
        gemm_g<128, 4, 1, true>(Qs, PITCH, g_wfrag + OFF_PROJ, 0, tid, c);
#pragma unroll
        for (int nt = 0; nt < 4; nt++){
            int col = ng * 32 + nt * 8 + 2 * t;
            float2 bv = *(const float2*)(b_proj + col);
            float2* p0 = (float2*)(Xs + r0 * PITCH + col);
            float2* p1 = (float2*)(Xs + (r0 + 8) * PITCH + col);
            float2 v0 = *p0, v1 = *p1;
            v0.x += c[nt][0] + bv.x; v0.y += c[nt][1] + bv.y;
            v1.x += c[nt][2] + bv.x; v1.y += c[nt][3] + bv.y;
            *p0 = v0; *p1 = v1;
        }
    }
    __syncthreads();
    layernorm(Xs, Ns, g2, b2, tid);
    __syncthreads();

    // ---- mlp1: t = gelu(n2 @ w_m1 + b_m1)  (N=256: 2 col-chunks) ----
#pragma unroll
    for (int ch = 0; ch < 2; ch++){
        float c[4][4];
        gemm_g<128, 4, 2, false>(Ns, PITCH, g_wfrag + OFF_M1, ch, tid, c);
#pragma unroll
        for (int nt = 0; nt < 4; nt++){
            int col = ng * 32 + nt * 8 + 2 * t;
            float2 bv = *(const float2*)(b_m1 + ch * 128 + col);
            float v[4] = {c[nt][0] + bv.x, c[nt][1] + bv.y,
                          c[nt][2] + bv.x, c[nt][3] + bv.y};
#pragma unroll
            for (int i = 0; i < 4; i++)
                v[i] = tf32f(0.5f * v[i] * (1.0f + erff(v[i] * 0.70710678118654752f)));
            *(float2*)(Ts + r0 * TPITCH + ch * 128 + col)       = make_float2(v[0], v[1]);
            *(float2*)(Ts + (r0 + 8) * TPITCH + ch * 128 + col) = make_float2(v[2], v[3]);
        }
    }
    __syncthreads();

    // ---- mlp2 + residual: x2 += t @ w_m2 + b_m2  (K=256) ----
    {
        float c[4][4];
        gemm_g<256, 4, 1, false>(Ts, TPITCH, g_wfrag + OFF_M2, 0, tid, c);
#pragma unroll
        for (int nt = 0; nt < 4; nt++){
            int col = ng * 32 + nt * 8 + 2 * t;
            float2 bv = *(const float2*)(b_m2 + col);
            float2* p0 = (float2*)(Xs + r0 * PITCH + col);
            float2* p1 = (float2*)(Xs + (r0 + 8) * PITCH + col);
            float2 v0 = *p0, v1 = *p1;
            v0.x += c[nt][0] + bv.x; v0.y += c[nt][1] + bv.y;
            v1.x += c[nt][2] + bv.x; v1.y += c[nt][3] + bv.y;
            *p0 = v0; *p1 = v1;
        }
    }
    __syncthreads();

    // ---- post: out = x2 @ w_post + b_post  (N=64, NT=2) ----
    {
        float c[2][4];
        gemm_g<128, 2, 1, true>(Xs, PITCH, g_wfrag + OFF_POST, 0, tid, c);
#pragma unroll
        for (int nt = 0; nt < 2; nt++){
            int col = ng * 16 + nt * 8 + 2 * t;
            float2 bv = *(const float2*)(b_post + col);
            *(float2*)(out + (tok0 + r0) * 64 + col) =
                make_float2(c[nt][0] + bv.x, c[nt][1] + bv.y);
            *(float2*)(out + (tok0 + r0 + 8) * 64 + col) =
                make_float2(c[nt][2] + bv.x, c[nt][3] + bv.y);
        }
    }
}

extern "C" void kernel_launch(void* const* d_in, const int* in_sizes, int n_in,
                              void* d_out, int out_size)
{
    const float* feats  = (const float*)d_in[0];
    const float* w_pre  = (const float*)d_in[1];
    const float* b_pre  = (const float*)d_in[2];
    const float* g1     = (const float*)d_in[3];
    const float* b1     = (const float*)d_in[4];
    const float* w_qkv  = (const float*)d_in[5];
    const float* b_qkv  = (const float*)d_in[6];
    const float* w_proj = (const float*)d_in[7];
    const float* b_proj = (const float*)d_in[8];
    const float* g2     = (const float*)d_in[9];
    const float* b2     = (const float*)d_in[10];
    const float* w_m1   = (const float*)d_in[11];
    const float* b_m1   = (const float*)d_in[12];
    const float* w_m2   = (const float*)d_in[13];
    const float* b_m2   = (const float*)d_in[14];
    const float* w_post = (const float*)d_in[15];
    const float* b_post = (const float*)d_in[16];
    float* out = (float*)d_out;

    // fragment-order + tf32 conversion of all weights (runs each replay; cheap)
    convert_w_kernel<<<64, 256>>>(w_pre,  128, 128, 4,  8192, OFF_PRE);
    convert_w_kernel<<<96, 256>>>(w_qkv,  384, 128, 4, 49152, OFF_QKV);
    convert_w_kernel<<<64, 256>>>(w_proj, 128, 128, 4, 16384, OFF_PROJ);
    convert_w_kernel<<<96, 256>>>(w_m1,   256, 128, 4, 32768, OFF_M1);
    convert_w_kernel<<<96, 256>>>(w_m2,   128, 128, 4, 32768, OFF_M2);
    convert_w_kernel<<<64, 256>>>(w_post,  64,  64, 2,  8192, OFF_POST);

    const int ntok    = in_sizes[0] / 64;   // C = 64
    const int nblocks = ntok / 64;          // PS = 64 tokens per window
    const size_t smem = (size_t)(5 * 64 * PITCH) * sizeof(float);   // 168960 B

    cudaFuncSetAttribute(fused_block_kernel,
                         cudaFuncAttributeMaxDynamicSharedMemorySize, (int)smem);

    fused_block_kernel<<<nblocks, THREADS, smem>>>(feats, b_pre, g1, b1,
                                                   b_qkv, b_proj, g2, b2,
                                                   b_m1, b_m2, b_post, out);
}

// round 11
// speedup vs baseline: 1.0027x; 1.0004x over previous
#include <cuda_runtime.h>
#include <math.h>

typedef unsigned int uint;

#define PITCH   132      // activation smem pitch: bank = 4*row + k -> conflict-free frags
#define TPITCH  260      // MLP hidden tile pitch (260 % 32 == 4 -> same property)
#define THREADS 512

// ---------------------------------------------------------------------------
// Pre-converted, fragment-ordered tf32 weights (shared by all CTAs).
// Layout: idx = ((((kc*NCHUNKS + nc)*4 + ng)*8 + kk8)*32 + lane)*(2*NT) + 2*nt + which
//   value = tf32( W[kc*64 + kk8*8 + t + which*4][nc*NCH + ng*NT*8 + nt*8 + g] )
//   (g = lane>>2, t = lane&3)
// ---------------------------------------------------------------------------
#define OFF_PRE   0
#define OFF_QKV   8192
#define OFF_PROJ  57344
#define OFF_M1    73728
#define OFF_M2    106496
#define OFF_POST  139264
#define WFRAG_TOTAL 147456

__device__ uint g_wfrag[WFRAG_TOTAL];

__device__ __forceinline__ uint tf32r(float f){
    uint u; asm("cvt.rna.tf32.f32 %0, %1;" : "=r"(u) : "f"(f)); return u;
}
__device__ __forceinline__ float tf32f(float f){ return __uint_as_float(tf32r(f)); }

// grid-stride weight converter: one output uint per logical index
__global__ void convert_w_kernel(const float* __restrict__ W, int N, int NCH, int NT,
                                 int total, int dstoff)
{
    const int nchunks = N / NCH;
    for (int i = blockIdx.x * blockDim.x + threadIdx.x; i < total;
         i += gridDim.x * blockDim.x){
        int tmp = i;
        int which = tmp & 1;        tmp >>= 1;
        int nt    = tmp % NT;       tmp /= NT;
        int lane  = tmp & 31;       tmp >>= 5;
        int kk8   = tmp & 7;        tmp >>= 3;
        int ng    = tmp & 3;        tmp >>= 2;
        int nc    = tmp % nchunks;  tmp /= nchunks;
        int kc    = tmp;
        int g = lane >> 2, t = lane & 3;
        int row = kc * 64 + kk8 * 8 + t + which * 4;
        int col = nc * NCH + ng * NT * 8 + nt * 8 + g;
        g_wfrag[dstoff + i] = tf32r(W[(size_t)row * N + col]);
    }
}

// m16n8k8 tf32 MMA, fp32 accumulate
__device__ __forceinline__ void mma8(float (&c)[4],
                                     uint a0, uint a1, uint a2, uint a3,
                                     uint b0, uint b1){
    asm("mma.sync.aligned.m16n8k8.row.col.f32.tf32.tf32.f32 "
        "{%0,%1,%2,%3}, {%4,%5,%6,%7}, {%8,%9}, {%0,%1,%2,%3};"
        : "+f"(c[0]), "+f"(c[1]), "+f"(c[2]), "+f"(c[3])
        : "r"(a0), "r"(a1), "r"(a2), "r"(a3), "r"(b0), "r"(b1));
}

// ---------------------------------------------------------------------------
// GEMM over one n-chunk using fragment-ordered global weights (no staging).
// Warp (mg, ng): rows mg*16..+15, cols ng*NT*8..+NT*8-1 within the chunk.
// ---------------------------------------------------------------------------
template<int KTOT, int NT, int NCHUNKS, bool CVT_A>
__device__ __forceinline__ void gemm_g(const float* __restrict__ As, int apitch,
                                       const uint* __restrict__ Wf, int nchunk,
                                       int tid, float (&c)[NT][4])
{
    const int warp = tid >> 5, lane = tid & 31;
    const int g = lane >> 2, t = lane & 3;
    const int mg = warp >> 2, ng = warp & 3;

#pragma unroll
    for (int nt = 0; nt < NT; nt++)
#pragma unroll
        for (int i = 0; i < 4; i++) c[nt][i] = 0.f;

    const float* a0p = As + (mg * 16 + g) * apitch + t;
    const float* a1p = a0p + 8 * apitch;

    constexpr int LSTRIDE = 2 * NT;                 // uints per lane per kk8
    constexpr int KKSTRIDE = 32 * LSTRIDE;          // per kk8 step
    constexpr int KCSTRIDE = NCHUNKS * 4 * 8 * KKSTRIDE / 8; // careful: per kchunk
    // per kchunk stride = NCHUNKS * 4(ng) * 8(kk8) * KKSTRIDE/ (kk8 factor already in) :
    // full: NCHUNKS*4*8*32*2*NT
    const uint* wbase = Wf + ((nchunk * 4 + ng) * 8) * KKSTRIDE + lane * LSTRIDE;

#pragma unroll
    for (int kc = 0; kc < KTOT / 64; kc++){
        const uint* wkc = wbase + kc * (NCHUNKS * 4 * 8 * KKSTRIDE);
#pragma unroll
        for (int kk8 = 0; kk8 < 8; kk8++){
            const int k = kc * 64 + kk8 * 8;
            float f0 = a0p[k],     f1 = a1p[k];
            float f2 = a0p[k + 4], f3 = a1p[k + 4];
            uint a0, a1, a2, a3;
            if (CVT_A){ a0 = tf32r(f0); a1 = tf32r(f1); a2 = tf32r(f2); a3 = tf32r(f3); }
            else      { a0 = __float_as_uint(f0); a1 = __float_as_uint(f1);
                        a2 = __float_as_uint(f2); a3 = __float_as_uint(f3); }
            const uint4* bp = (const uint4*)(wkc + kk8 * KKSTRIDE);
#pragma unroll
            for (int p = 0; p < NT / 2; p++){
                uint4 bv = bp[p];
                mma8(c[2*p],     a0, a1, a2, a3, bv.x, bv.y);
                mma8(c[2*p + 1], a0, a1, a2, a3, bv.z, bv.w);
            }
        }
    }
    (void)KCSTRIDE;
}

// ---------------------------------------------------------------------------
// LayerNorm over 128 cols -> tf32-rounded output
// ---------------------------------------------------------------------------
__device__ __forceinline__ void layernorm(const float* __restrict__ Xs, float* __restrict__ Ns,
                                          const float* __restrict__ g, const float* __restrict__ b,
                                          int tid)
{
    const int row = tid >> 3, sub = tid & 7;
    const float* xr = Xs + row * PITCH;
    float s = 0.f, s2 = 0.f;
#pragma unroll
    for (int i = 0; i < 16; i++){
        float v = xr[sub + i * 8];
        s += v; s2 = fmaf(v, v, s2);
    }
#pragma unroll
    for (int o = 4; o; o >>= 1){
        s  += __shfl_xor_sync(0xffffffffu, s,  o);
        s2 += __shfl_xor_sync(0xffffffffu, s2, o);
    }
    float mu  = s  * (1.f / 128.f);
    float var = s2 * (1.f / 128.f) - mu * mu;
    float rs  = rsqrtf(var + 1e-5f);
    float* nr = Ns + row * PITCH;
#pragma unroll
    for (int i = 0; i < 16; i++){
        int c = sub + i * 8;
        nr[c] = tf32f((xr[c] - mu) * rs * g[c] + b[c]);
    }
}

// ---------------------------------------------------------------------------
// Windowed attention on the tensor pipe (unchanged from R6).
// ---------------------------------------------------------------------------
__device__ __forceinline__ void attention_phase(float* Qs, const float* Ks, const float* Vs, int tid)
{
    const int warp = tid >> 5;
    const int lane = tid & 31;
    const int g = lane >> 2, t = lane & 3;
    const int h = warp >> 1;
    const int s = warp & 1;
    const int co = h * 16;

    const int src0 = (lane & 28) | (t >> 1);
    const int src1 = src0 + 2;
    const bool odd = (t & 1);

#pragma unroll
    for (int mt = 0; mt < 2; mt++){
        const int m0 = s * 32 + mt * 16;

        float sc[8][4];
#pragma unroll
        for (int nb = 0; nb < 8; nb++){
            sc[nb][0] = sc[nb][1] = sc[nb][2] = sc[nb][3] = 0.f;
        }
#pragma unroll
        for (int k0 = 0; k0 < 16; k0 += 8){
            const float* qp = Qs + (m0 + g) * PITCH + co + k0 + t;
            uint a0 = __float_as_uint(qp[0]);
            uint a1 = __float_as_uint(qp[8 * PITCH]);
            uint a2 = __float_as_uint(qp[4]);
            uint a3 = __float_as_uint(qp[8 * PITCH + 4]);
#pragma unroll
            for (int nb = 0; nb < 8; nb++){
                const float* kp = Ks + (8 * nb + g) * PITCH + co + k0 + t;
                uint b0 = __float_as_uint(kp[0]);
                uint b1 = __float_as_uint(kp[4]);
                mma8(sc[nb], a0, a1, a2, a3, b0, b1);
            }
        }

        float mx0 = -1e30f, mx1 = -1e30f;
#pragma unroll
        for (int nb = 0; nb < 8; nb++){
            mx0 = fmaxf(mx0, fmaxf(sc[nb][0], sc[nb][1]));
            mx1 = fmaxf(mx1, fmaxf(sc[nb][2], sc[nb][3]));
        }
        mx0 = fmaxf(mx0, __shfl_xor_sync(0xffffffffu, mx0, 1));
        mx0 = fmaxf(mx0, __shfl_xor_sync(0xffffffffu, mx0, 2));
        mx1 = fmaxf(mx1, __shfl_xor_sync(0xffffffffu, mx1, 1));
        mx1 = fmaxf(mx1, __shfl_xor_sync(0xffffffffu, mx1, 2));

        float l0 = 0.f, l1 = 0.f;
#pragma unroll
        for (int nb = 0; nb < 8; nb++){
            float p0 = __expf((sc[nb][0] - mx0) * 0.25f);
            float p1 = __expf((sc[nb][1] - mx0) * 0.25f);
            float p2 = __expf((sc[nb][2] - mx1) * 0.25f);
            float p3 = __expf((sc[nb][3] - mx1) * 0.25f);
            l0 += p0 + p1;  l1 += p2 + p3;
            sc[nb][0] = __uint_as_float(tf32r(p0));
            sc[nb][1] = __uint_as_float(tf32r(p1));
            sc[nb][2] = __uint_as_float(tf32r(p2));
            sc[nb][3] = __uint_as_float(tf32r(p3));
        }
        l0 += __shfl_xor_sync(0xffffffffu, l0, 1);
        l0 += __shfl_xor_sync(0xffffffffu, l0, 2);
        l1 += __shfl_xor_sync(0xffffffffu, l1, 1);
        l1 += __shfl_xor_sync(0xffffffffu, l1, 2);

        float oc[2][4];
        oc[0][0]=oc[0][1]=oc[0][2]=oc[0][3]=0.f;
        oc[1][0]=oc[1][1]=oc[1][2]=oc[1][3]=0.f;
#pragma unroll
        for (int kb = 0; kb < 8; kb++){
            float p0 = sc[kb][0], p1 = sc[kb][1], p2 = sc[kb][2], p3 = sc[kb][3];
            float q00 = __shfl_sync(0xffffffffu, p0, src0);
            float q01 = __shfl_sync(0xffffffffu, p1, src0);
            float q02 = __shfl_sync(0xffffffffu, p0, src1);
            float q03 = __shfl_sync(0xffffffffu, p1, src1);
            float q10 = __shfl_sync(0xffffffffu, p2, src0);
            float q11 = __shfl_sync(0xffffffffu, p3, src0);
            float q12 = __shfl_sync(0xffffffffu, p2, src1);
            float q13 = __shfl_sync(0xffffffffu, p3, src1);
            uint a0 = __float_as_uint(odd ? q01 : q00);
            uint a1 = __float_as_uint(odd ? q11 : q10);
            uint a2 = __float_as_uint(odd ? q03 : q02);
            uint a3 = __float_as_uint(odd ? q13 : q12);
#pragma unroll
            for (int nb2 = 0; nb2 < 2; nb2++){
                const float* vp = Vs + (8 * kb + t) * PITCH + co + nb2 * 8 + g;
                uint b0 = __float_as_uint(vp[0]);
                uint b1 = __float_as_uint(vp[4 * PITCH]);
                mma8(oc[nb2], a0, a1, a2, a3, b0, b1);
            }
        }
        float i0 = 1.0f / l0, i1 = 1.0f / l1;
#pragma unroll
        for (int nb2 = 0; nb2 < 2; nb2++){
            float* op0 = Qs + (m0 + g) * PITCH + co + nb2 * 8 + 2 * t;
            float* op1 = op0 + 8 * PITCH;
            *(float2*)op0 = make_float2(oc[nb2][0] * i0, oc[nb2][1] * i0);
            *(float2*)op1 = make_float2(oc[nb2][2] * i1, oc[nb2][3] * i1);
        }
    }
}

// ---------------------------------------------------------------------------
// Fused transformer block: one CTA = one 64-token window.
// ---------------------------------------------------------------------------
extern __shared__ float smbuf[];

__global__ void __launch_bounds__(THREADS, 1)
fused_block_kernel(const float* __restrict__ feats,
                   const float* __restrict__ b_pre,
                   const float* __restrict__ g1,   const float* __restrict__ b1,
                   const float* __restrict__ b_qkv,
                   const float* __restrict__ b_proj,
                   const float* __restrict__ g2,   const float* __restrict__ b2,
                   const float* __restrict__ b_m1, const float* __restrict__ b_m2,
                   const float* __restrict__ b_post,
                   float* __restrict__ out)
{
    float* Xs = smbuf;                  // residual stream (fp32)     [64][132]
    float* Ns = smbuf + 64 * PITCH;     // LN out / staged feats (tf32-rounded)
    float* Qs = smbuf + 2 * 64 * PITCH; // q -> attention output o
    float* Ks = smbuf + 3 * 64 * PITCH; // k -> MLP hidden (pitch 260 spans Ks+Vs)
    float* Vs = smbuf + 4 * 64 * PITCH; // v
    float* Ts = Ks;

    const int tid  = threadIdx.x;
    const int warp = tid >> 5, lane = tid & 31;
    const int g    = lane >> 2, t = lane & 3;
    const int mg   = warp >> 2, ng = warp & 3;
    const int r0   = mg * 16 + g;
    const size_t tok0 = (size_t)blockIdx.x * 64;

    // stage feats tile [64][64] into Ns cols 0..63 (tf32-rounded)
    for (int i = tid; i < 64 * 16; i += THREADS){
        int tk = i >> 4, c4 = i & 15;
        float4 v = ((const float4*)(feats + (tok0 + tk) * 64))[c4];
        uint4 o = make_uint4(tf32r(v.x), tf32r(v.y), tf32r(v.z), tf32r(v.w));
        *(uint4*)((uint*)Ns + tk * PITCH + c4 * 4) = o;
    }
    __syncthreads();

    // ---- pre: x2 = feats @ w_pre + b_pre  (K=64 -> N=128) ----
    {
        float c[4][4];
        gemm_g<64, 4, 1, false>(Ns, PITCH, g_wfrag + OFF_PRE, 0, tid, c);
#pragma unroll
        for (int nt = 0; nt < 4; nt++){
            int col = ng * 32 + nt * 8 + 2 * t;
            float2 bv = *(const float2*)(b_pre + col);
            *(float2*)(Xs + r0 * PITCH + col)       = make_float2(c[nt][0] + bv.x, c[nt][1] + bv.y);
            *(float2*)(Xs + (r0 + 8) * PITCH + col) = make_float2(c[nt][2] + bv.x, c[nt][3] + bv.y);
        }
    }
    __syncthreads();
    layernorm(Xs, Ns, g1, b1, tid);
    __syncthreads();

    // ---- qkv: 3 col-chunks of w_qkv (N=384), K=128 ----
    {
        float* dsts[3] = {Qs, Ks, Vs};
#pragma unroll
        for (int ch = 0; ch < 3; ch++){
            float c[4][4];
            gemm_g<128, 4, 3, false>(Ns, PITCH, g_wfrag + OFF_QKV, ch, tid, c);
            float* dst = dsts[ch];
#pragma unroll
            for (int nt = 0; nt < 4; nt++){
                int col = ng * 32 + nt * 8 + 2 * t;
                float2 bv = *(const float2*)(b_qkv + ch * 128 + col);
                *(float2*)(dst + r0 * PITCH + col) =
                    make_float2(tf32f(c[nt][0] + bv.x), tf32f(c[nt][1] + bv.y));
                *(float2*)(dst + (r0 + 8) * PITCH + col) =
                    make_float2(tf32f(c[nt][2] + bv.x), tf32f(c[nt][3] + bv.y));
            }
        }
    }
    __syncthreads();

    attention_phase(Qs, Ks, Vs, tid);   // o -> Qs (fp32), tensor-pipe MMA
    __syncthreads();

    // ---- proj + residual: x2 += o @ w_proj + b_proj ----
    {
        float c[4][4];
        gemm_g<128, 4, 1, true>(Qs, PITCH, g_wfrag + OFF_PROJ, 0, tid, c);
#pragma unroll
        for (int nt = 0; nt < 4; nt++){
            int col = ng * 32 + nt * 8 + 2 * t;
            float2 bv = *(const float2*)(b_proj + col);
            float2* p0 = (float2*)(Xs + r0 * PITCH + col);
            float2* p1 = (float2*)(Xs + (r0 + 8) * PITCH + col);
            float2 v0 = *p0, v1 = *p1;
            v0.x += c[nt][0] + bv.x; v0.y += c[nt][1] + bv.y;
            v1.x += c[nt][2] + bv.x; v1.y += c[nt][3] + bv.y;
            *p0 = v0; *p1 = v1;
        }
    }
    __syncthreads();
    layernorm(Xs, Ns, g2, b2, tid);
    __syncthreads();

    // ---- mlp1: t = gelu(n2 @ w_m1 + b_m1)  (N=256: 2 col-chunks) ----
#pragma unroll
    for (int ch = 0; ch < 2; ch++){
        float c[4][4];
        gemm_g<128, 4, 2, false>(Ns, PITCH, g_wfrag + OFF_M1, ch, tid, c);
#pragma unroll
        for (int nt = 0; nt < 4; nt++){
            int col = ng * 32 + nt * 8 + 2 * t;
            float2 bv = *(const float2*)(b_m1 + ch * 128 + col);
            float v[4] = {c[nt][0] + bv.x, c[nt][1] + bv.y,
                          c[nt][2] + bv.x, c[nt][3] + bv.y};
#pragma unroll
            for (int i = 0; i < 4; i++)
                v[i] = tf32f(0.5f * v[i] * (1.0f + erff(v[i] * 0.70710678118654752f)));
            *(float2*)(Ts + r0 * TPITCH + ch * 128 + col)       = make_float2(v[0], v[1]);
            *(float2*)(Ts + (r0 + 8) * TPITCH + ch * 128 + col) = make_float2(v[2], v[3]);
        }
    }
    __syncthreads();

    // ---- mlp2 + residual: x2 += t @ w_m2 + b_m2  (K=256) ----
    {
        float c[4][4];
        gemm_g<256, 4, 1, false>(Ts, TPITCH, g_wfrag + OFF_M2, 0, tid, c);
#pragma unroll
        for (int nt = 0; nt < 4; nt++){
            int col = ng * 32 + nt * 8 + 2 * t;
            float2 bv = *(const float2*)(b_m2 + col);
            float2* p0 = (float2*)(Xs + r0 * PITCH + col);
            float2* p1 = (float2*)(Xs + (r0 + 8) * PITCH + col);
            float2 v0 = *p0, v1 = *p1;
            v0.x += c[nt][0] + bv.x; v0.y += c[nt][1] + bv.y;
            v1.x += c[nt][2] + bv.x; v1.y += c[nt][3] + bv.y;
            *p0 = v0; *p1 = v1;
        }
    }
    __syncthreads();

    // ---- post: out = x2 @ w_post + b_post  (N=64, NT=2) ----
    {
        float c[2][4];
        gemm_g<128, 2, 1, true>(Xs, PITCH, g_wfrag + OFF_POST, 0, tid, c);
#pragma unroll
        for (int nt = 0; nt < 2; nt++){
            int col = ng * 16 + nt * 8 + 2 * t;
            float2 bv = *(const float2*)(b_post + col);
            *(float2*)(out + (tok0 + r0) * 64 + col) =
                make_float2(c[nt][0] + bv.x, c[nt][1] + bv.y);
            *(float2*)(out + (tok0 + r0 + 8) * 64 + col) =
                make_float2(c[nt][2] + bv.x, c[nt][3] + bv.y);
        }
    }
}

extern "C" void kernel_launch(void* const* d_in, const int* in_sizes, int n_in,
                              void* d_out, int out_size)
{
    const float* feats  = (const float*)d_in[0];
    const float* w_pre  = (const float*)d_in[1];
    const float* b_pre  = (const float*)d_in[2];
    const float* g1     = (const float*)d_in[3];
    const float* b1     = (const float*)d_in[4];
    const float* w_qkv  = (const float*)d_in[5];
    const float* b_qkv  = (const float*)d_in[6];
    const float* w_proj = (const float*)d_in[7];
    const float* b_proj = (const float*)d_in[8];
    const float* g2     = (const float*)d_in[9];
    const float* b2     = (const float*)d_in[10];
    const float* w_m1   = (const float*)d_in[11];
    const float* b_m1   = (const float*)d_in[12];
    const float* w_m2   = (const float*)d_in[13];
    const float* b_m2   = (const float*)d_in[14];
    const float* w_post = (const float*)d_in[15];
    const float* b_post = (const float*)d_in[16];
    float* out = (float*)d_out;

    // fragment-order + tf32 conversion of all weights (runs each replay; cheap)
    convert_w_kernel<<<64, 256>>>(w_pre,  128, 128, 4,  8192, OFF_PRE);
    convert_w_kernel<<<96, 256>>>(w_qkv,  384, 128, 4, 49152, OFF_QKV);
    convert_w_kernel<<<64, 256>>>(w_proj, 128, 128, 4, 16384, OFF_PROJ);
    convert_w_kernel<<<96, 256>>>(w_m1,   256, 128, 4, 32768, OFF_M1);
    convert_w_kernel<<<96, 256>>>(w_m2,   128, 128, 4, 32768, OFF_M2);
    convert_w_kernel<<<64, 256>>>(w_post,  64,  64, 2,  8192, OFF_POST);

    const int ntok    = in_sizes[0] / 64;   // C = 64
    const int nblocks = ntok / 64;          // PS = 64 tokens per window
    const size_t smem = (size_t)(5 * 64 * PITCH) * sizeof(float);   // 168960 B

    cudaFuncSetAttribute(fused_block_kernel,
                         cudaFuncAttributeMaxDynamicSharedMemorySize, (int)smem);

    fused_block_kernel<<<nblocks, THREADS, smem>>>(feats, b_pre, g1, b1,
                                                   b_qkv, b_proj, g2, b2,
                                                   b_m1, b_m2, b_post, out);
}